// round 1
// baseline (speedup 1.0000x reference)
#include <cuda_runtime.h>
#include <math.h>
#include <float.h>

#define NPIL 60000
#define PPTS 32

// 65 moment accumulators: [0..9] = sum(feats), [10..64] = upper-tri sum(feats x feats)
static __device__ float g_acc[65];
// per-channel folded params, 12 floats each:
// [0..3]=Wc (x,y,z,w merged+BN-scaled) [4..6]=a*W[4:7] [7..9]=a*W[7:10] [10]=b [11]=pad
static __device__ float g_params[64 * 12];

__global__ void k_init() {
    int t = threadIdx.x;
    if (t < 65) g_acc[t] = 0.0f;
}

__global__ void __launch_bounds__(256) k_stats(const float4* __restrict__ pts,
                                               const int* __restrict__ nvs,
                                               const int4* __restrict__ coords) {
    __shared__ float sred[8 * 65];
    const int lane = threadIdx.x & 31;
    const int warp = threadIdx.x >> 5;
    const int gw = blockIdx.x * 8 + warp;
    const int nw = gridDim.x * 8;

    float acc[65];
#pragma unroll
    for (int k = 0; k < 65; k++) acc[k] = 0.0f;

    for (int i = gw; i < NPIL; i += nw) {
        float4 q = pts[i * PPTS + lane];
        int nv = nvs[i];
        // sum of xyz over ALL 32 points (reference sums unmasked, divides by nv)
        float sx = q.x, sy = q.y, sz = q.z;
#pragma unroll
        for (int s = 16; s > 0; s >>= 1) {
            sx += __shfl_xor_sync(0xffffffffu, sx, s);
            sy += __shfl_xor_sync(0xffffffffu, sy, s);
            sz += __shfl_xor_sync(0xffffffffu, sz, s);
        }
        float inv = 1.0f / (float)nv;
        float mx = sx * inv, my = sy * inv, mz = sz * inv;
        int4 c = coords[i];
        float cx = (float)c.w * 0.2f + 0.1f;
        float cy = (float)c.z * 0.2f - 39.9f;
        float cz = (float)c.y * 4.0f - 1.0f;
        float valid = (lane < nv) ? 1.0f : 0.0f;
        float f[10];
        f[0] = q.x * valid;        f[1] = q.y * valid;        f[2] = q.z * valid;
        f[3] = q.w * valid;
        f[4] = (q.x - mx) * valid; f[5] = (q.y - my) * valid; f[6] = (q.z - mz) * valid;
        f[7] = (q.x - cx) * valid; f[8] = (q.y - cy) * valid; f[9] = (q.z - cz) * valid;
#pragma unroll
        for (int k = 0; k < 10; k++) acc[k] += f[k];
        int idx = 10;
#pragma unroll
        for (int a = 0; a < 10; a++)
#pragma unroll
            for (int b = a; b < 10; b++)
                acc[idx++] += f[a] * f[b];
    }

    // warp reduce each accumulator, stage per-warp, block reduce, one atomic set per block
#pragma unroll
    for (int k = 0; k < 65; k++) {
        float v = acc[k];
#pragma unroll
        for (int s = 16; s > 0; s >>= 1) v += __shfl_xor_sync(0xffffffffu, v, s);
        if (lane == 0) sred[warp * 65 + k] = v;
    }
    __syncthreads();
    int t = threadIdx.x;
    if (t < 65) {
        float s = 0.0f;
#pragma unroll
        for (int w = 0; w < 8; w++) s += sred[w * 65 + t];
        atomicAdd(&g_acc[t], s);
    }
}

__global__ void k_bn(const float* __restrict__ W, const float* __restrict__ gamma,
                     const float* __restrict__ beta) {
    int o = threadIdx.x;
    if (o >= 64) return;
    double w[10];
#pragma unroll
    for (int c = 0; c < 10; c++) w[c] = (double)W[o * 10 + c];
    const double NP = (double)NPIL * (double)PPTS;
    double mean = 0.0;
#pragma unroll
    for (int c = 0; c < 10; c++) mean += w[c] * (double)g_acc[c];
    mean /= NP;
    double e2 = 0.0;
    int idx = 10;
#pragma unroll
    for (int a = 0; a < 10; a++)
#pragma unroll
        for (int b = a; b < 10; b++) {
            double m = (double)g_acc[idx++];
            e2 += w[a] * w[b] * m * ((a == b) ? 1.0 : 2.0);
        }
    e2 /= NP;
    double var = e2 - mean * mean;
    double aa = (double)gamma[o] / sqrt(var + 1e-3);
    double bb = (double)beta[o] - mean * aa;
    float* p = g_params + o * 12;
    p[0] = (float)(aa * (w[0] + w[4] + w[7]));
    p[1] = (float)(aa * (w[1] + w[5] + w[8]));
    p[2] = (float)(aa * (w[2] + w[6] + w[9]));
    p[3] = (float)(aa * w[3]);
    p[4] = (float)(aa * w[4]);
    p[5] = (float)(aa * w[5]);
    p[6] = (float)(aa * w[6]);
    p[7] = (float)(aa * w[7]);
    p[8] = (float)(aa * w[8]);
    p[9] = (float)(aa * w[9]);
    p[10] = (float)bb;
    p[11] = 0.0f;
}

__global__ void __launch_bounds__(256) k_out(const float4* __restrict__ pts,
                                             const int* __restrict__ nvs,
                                             const int4* __restrict__ coords,
                                             float* __restrict__ out) {
    __shared__ float4 sp[8][32];
    const int lane = threadIdx.x & 31;
    const int warp = threadIdx.x >> 5;
    const int gw = blockIdx.x * 8 + warp;
    const int nw = gridDim.x * 8;

    // params for channels (lane) and (lane+32); per channel: 3 float4s
    const float4* pp = (const float4*)g_params;
    float4 wc0 = pp[lane * 3 + 0];
    float4 m0v = pp[lane * 3 + 1];   // {wm.x, wm.y, wm.z, wt.x}
    float4 t0v = pp[lane * 3 + 2];   // {wt.y, wt.z, b, pad}
    float4 wc1 = pp[(lane + 32) * 3 + 0];
    float4 m1v = pp[(lane + 32) * 3 + 1];
    float4 t1v = pp[(lane + 32) * 3 + 2];

    for (int i = gw; i < NPIL; i += nw) {
        float4 q = pts[i * PPTS + lane];
        sp[warp][lane] = q;
        __syncwarp();
        int nv = nvs[i];
        float sx = q.x, sy = q.y, sz = q.z;
#pragma unroll
        for (int s = 16; s > 0; s >>= 1) {
            sx += __shfl_xor_sync(0xffffffffu, sx, s);
            sy += __shfl_xor_sync(0xffffffffu, sy, s);
            sz += __shfl_xor_sync(0xffffffffu, sz, s);
        }
        float inv = 1.0f / (float)nv;
        float mx = sx * inv, my = sy * inv, mz = sz * inv;
        int4 c = coords[i];
        float cx = (float)c.w * 0.2f + 0.1f;
        float cy = (float)c.z * 0.2f - 39.9f;
        float cz = (float)c.y * 4.0f - 1.0f;

        float pb0 = t0v.z - (mx * m0v.x + my * m0v.y + mz * m0v.z)
                          - (cx * m0v.w + cy * t0v.x + cz * t0v.y);
        float pb1 = t1v.z - (mx * m1v.x + my * m1v.y + mz * m1v.z)
                          - (cx * m1v.w + cy * t1v.x + cz * t1v.y);

        // masked points (if any) contribute exactly b_o pre-ReLU
        float a0 = (nv < PPTS) ? t0v.z : -FLT_MAX;
        float a1 = (nv < PPTS) ? t1v.z : -FLT_MAX;

        for (int p = 0; p < nv; p++) {
            float4 r = sp[warp][p];
            float x0 = pb0 + r.x * wc0.x + r.y * wc0.y + r.z * wc0.z + r.w * wc0.w;
            float x1 = pb1 + r.x * wc1.x + r.y * wc1.y + r.z * wc1.z + r.w * wc1.w;
            a0 = fmaxf(a0, x0);
            a1 = fmaxf(a1, x1);
        }
        out[i * 64 + lane]      = fmaxf(a0, 0.0f);
        out[i * 64 + 32 + lane] = fmaxf(a1, 0.0f);
        __syncwarp();
    }
}

extern "C" void kernel_launch(void* const* d_in, const int* in_sizes, int n_in,
                              void* d_out, int out_size) {
    const float4* feats  = (const float4*)d_in[0];
    const int*    nvs    = (const int*)d_in[1];
    const int4*   coords = (const int4*)d_in[2];
    const float*  W      = (const float*)d_in[3];
    const float*  gamma  = (const float*)d_in[4];
    const float*  beta   = (const float*)d_in[5];
    float* out = (float*)d_out;

    k_init<<<1, 128>>>();
    k_stats<<<296, 256>>>(feats, nvs, coords);
    k_bn<<<1, 64>>>(W, gamma, beta);
    k_out<<<1184, 256>>>(feats, nvs, coords, out);
}